// round 1
// baseline (speedup 1.0000x reference)
#include <cuda_runtime.h>
#include <math.h>

// Problem constants
#define M_TOK 4096      // B*S = 2*2048
#define HID   1024
#define NEXP  8
#define CAP   1536      // int(2*2048*1.5*2/8)

static const size_t D_SZ = (size_t)M_TOK * NEXP * CAP;   // 50,331,648 per tensor

// scratch for h = relu(x @ w1^T + b1)  (16 MB)
__device__ float g_h[(size_t)M_TOK * HID];

// ---------------------------------------------------------------------------
// packed f32x2 helpers (sm_103a)
// ---------------------------------------------------------------------------
__device__ __forceinline__ unsigned long long pack2(float lo, float hi) {
    unsigned long long r;
    asm("mov.b64 %0, {%1, %2};" : "=l"(r) : "f"(lo), "f"(hi));
    return r;
}
__device__ __forceinline__ void fma2(unsigned long long& acc,
                                     unsigned long long a,
                                     unsigned long long b) {
    asm("fma.rn.f32x2 %0, %1, %2, %0;" : "+l"(acc) : "l"(a), "l"(b));
}
__device__ __forceinline__ void unpack2(unsigned long long v, float& lo, float& hi) {
    asm("mov.b64 {%0, %1}, %2;" : "=f"(lo), "=f"(hi) : "l"(v));
}

// ---------------------------------------------------------------------------
// zero-fill kernel for dispatch + combine tensors (d_out is poisoned)
// ---------------------------------------------------------------------------
__global__ void zero_kernel(float4* __restrict__ p, long n4) {
    long i = (long)blockIdx.x * blockDim.x + threadIdx.x;
    long stride = (long)gridDim.x * blockDim.x;
    float4 z = make_float4(0.f, 0.f, 0.f, 0.f);
    for (; i < n4; i += stride) p[i] = z;
}

// ---------------------------------------------------------------------------
// GEMM + bias + ReLU:  g_h[m,n] = relu( sum_k x[m,k]*w1[n,k] + b1[n] )
// NT GEMM, 128x128 block tile, BK=16, 256 threads, 8x8 per thread,
// inner loop uses packed fma.rn.f32x2 (M-pairs packed, B duplicated in SMEM).
// ---------------------------------------------------------------------------
#define BM 128
#define BN 128
#define BK 16

__global__ __launch_bounds__(256, 2)
void gemm_relu_kernel(const float* __restrict__ A,    // [M_TOK, HID]
                      const float* __restrict__ B,    // [HID(out), HID(in)] = w1
                      const float* __restrict__ bias) // [HID]
{
    __shared__ __align__(16) float              As[BK][BM];
    __shared__ __align__(16) unsigned long long Bs[BK][BN];  // (b,b) duplicated

    const int tid = threadIdx.x;
    const int m0  = blockIdx.y * BM;
    const int n0  = blockIdx.x * BN;
    const int ty  = tid >> 4;        // 0..15
    const int tx  = tid & 15;        // 0..15

    unsigned long long acc[4][8];
#pragma unroll
    for (int i = 0; i < 4; i++)
#pragma unroll
        for (int j = 0; j < 8; j++) acc[i][j] = 0ull;

    for (int k0 = 0; k0 < HID; k0 += BK) {
        // ---- load A tile (transpose to [k][m]) ----
#pragma unroll
        for (int it = 0; it < 2; it++) {
            int idx = tid + it * 256;            // 0..511
            int row = idx >> 2;                  // 0..127
            int c4  = (idx & 3) * 4;             // 0,4,8,12
            float4 v = *(const float4*)&A[(size_t)(m0 + row) * HID + k0 + c4];
            As[c4 + 0][row] = v.x;
            As[c4 + 1][row] = v.y;
            As[c4 + 2][row] = v.z;
            As[c4 + 3][row] = v.w;
        }
        // ---- load B tile, duplicated (b,b) pairs, transpose to [k][n] ----
#pragma unroll
        for (int it = 0; it < 2; it++) {
            int idx = tid + it * 256;
            int row = idx >> 2;
            int c4  = (idx & 3) * 4;
            float4 v = *(const float4*)&B[(size_t)(n0 + row) * HID + k0 + c4];
            Bs[c4 + 0][row] = pack2(v.x, v.x);
            Bs[c4 + 1][row] = pack2(v.y, v.y);
            Bs[c4 + 2][row] = pack2(v.z, v.z);
            Bs[c4 + 3][row] = pack2(v.w, v.w);
        }
        __syncthreads();

#pragma unroll
        for (int kk = 0; kk < BK; kk++) {
            // a pairs: 8 consecutive M-rows -> 4 packed (m, m+1) values
            ulonglong2 t0 = *(const ulonglong2*)&As[kk][ty * 8];
            ulonglong2 t1 = *(const ulonglong2*)&As[kk][ty * 8 + 4];
            unsigned long long a2[4] = { t0.x, t0.y, t1.x, t1.y };
            // b: 8 columns, each already duplicated (b,b)
            ulonglong2 u0 = *(const ulonglong2*)&Bs[kk][tx * 8 + 0];
            ulonglong2 u1 = *(const ulonglong2*)&Bs[kk][tx * 8 + 2];
            ulonglong2 u2 = *(const ulonglong2*)&Bs[kk][tx * 8 + 4];
            ulonglong2 u3 = *(const ulonglong2*)&Bs[kk][tx * 8 + 6];
            unsigned long long b2[8] = { u0.x, u0.y, u1.x, u1.y,
                                         u2.x, u2.y, u3.x, u3.y };
#pragma unroll
            for (int i = 0; i < 4; i++)
#pragma unroll
                for (int j = 0; j < 8; j++)
                    fma2(acc[i][j], a2[i], b2[j]);
        }
        __syncthreads();
    }

    // ---- epilogue: +bias, ReLU, store ----
    const int col = n0 + tx * 8;
    float bb[8];
#pragma unroll
    for (int j = 0; j < 8; j++) bb[j] = bias[col + j];

#pragma unroll
    for (int i2 = 0; i2 < 4; i2++) {
        float r0[8], r1[8];
#pragma unroll
        for (int j = 0; j < 8; j++) {
            unpack2(acc[i2][j], r0[j], r1[j]);
            r0[j] = fmaxf(r0[j] + bb[j], 0.f);
            r1[j] = fmaxf(r1[j] + bb[j], 0.f);
        }
        int row0 = m0 + ty * 8 + i2 * 2;
        float* c0 = &g_h[(size_t)row0 * HID + col];
        float* c1 = &g_h[(size_t)(row0 + 1) * HID + col];
        *(float4*)(c0 + 0) = make_float4(r0[0], r0[1], r0[2], r0[3]);
        *(float4*)(c0 + 4) = make_float4(r0[4], r0[5], r0[6], r0[7]);
        *(float4*)(c1 + 0) = make_float4(r1[0], r1[1], r1[2], r1[3]);
        *(float4*)(c1 + 4) = make_float4(r1[4], r1[5], r1[6], r1[7]);
    }
}

// ---------------------------------------------------------------------------
// Router: per token -> logits[8], softmax, top-2, scatter into dispatch /
// combine slot 0, write router_probs.
// Block = 256 threads per token; warp e computes expert e's dot product.
// ---------------------------------------------------------------------------
__global__ void router_kernel(const float* __restrict__ w2,  // [NEXP, HID]
                              const float* __restrict__ b2,  // [NEXP]
                              float* __restrict__ out)
{
    const int m   = blockIdx.x;          // token
    const int tid = threadIdx.x;

    __shared__ __align__(16) float hs[HID];
    __shared__ float logits[NEXP];

    // load h row into smem (256 * float4 = 1024 floats)
    const float4* hrow = (const float4*)&g_h[(size_t)m * HID];
    ((float4*)hs)[tid] = hrow[tid];
    __syncthreads();

    const int e    = tid >> 5;           // warp id = expert
    const int lane = tid & 31;
    const float4* w2row = (const float4*)&w2[(size_t)e * HID];
    const float4* hs4   = (const float4*)hs;

    float sum = 0.f;
#pragma unroll
    for (int i = 0; i < 8; i++) {
        float4 a = hs4[lane + i * 32];
        float4 b = w2row[lane + i * 32];
        sum += a.x * b.x + a.y * b.y + a.z * b.z + a.w * b.w;
    }
#pragma unroll
    for (int off = 16; off > 0; off >>= 1)
        sum += __shfl_xor_sync(0xFFFFFFFFu, sum, off);
    if (lane == 0) logits[e] = sum + b2[e];
    __syncthreads();

    if (tid == 0) {
        float l[NEXP], p[NEXP];
        float mx = -1e30f;
#pragma unroll
        for (int i = 0; i < NEXP; i++) { l[i] = logits[i]; mx = fmaxf(mx, l[i]); }
        float s = 0.f;
#pragma unroll
        for (int i = 0; i < NEXP; i++) { p[i] = expf(l[i] - mx); s += p[i]; }
        float inv = 1.f / s;
#pragma unroll
        for (int i = 0; i < NEXP; i++) p[i] *= inv;

        // router_probs
        float* rp = out + 2 * D_SZ + (size_t)m * NEXP;
#pragma unroll
        for (int i = 0; i < NEXP; i++) rp[i] = p[i];

        // top-2 (ties -> lowest index first, matching jax.lax.top_k)
        int i1 = 0;
#pragma unroll
        for (int i = 1; i < NEXP; i++) if (p[i] > p[i1]) i1 = i;
        int i2 = -1;
#pragma unroll
        for (int i = 0; i < NEXP; i++) {
            if (i == i1) continue;
            if (i2 < 0 || p[i] > p[i2]) i2 = i;
        }
        float denom = p[i1] + p[i2];

        size_t base = (size_t)m * NEXP * CAP;           // slot 0 of expert e
        out[base + (size_t)i1 * CAP] = 1.0f;            // dispatch
        out[base + (size_t)i2 * CAP] = 1.0f;
        out[D_SZ + base + (size_t)i1 * CAP] = p[i1] / denom;  // combine
        out[D_SZ + base + (size_t)i2 * CAP] = p[i2] / denom;
    }
}

// ---------------------------------------------------------------------------
// Aux loss: deterministic tree reduction of mean prob per expert.
// ---------------------------------------------------------------------------
__global__ void aux_kernel(float* __restrict__ out)
{
    __shared__ float s[NEXP][256];
    const int tid = threadIdx.x;
    const float* rp = out + 2 * D_SZ;

    float loc[NEXP];
#pragma unroll
    for (int e = 0; e < NEXP; e++) loc[e] = 0.f;
    for (int t = tid; t < M_TOK; t += 256) {
#pragma unroll
        for (int e = 0; e < NEXP; e++) loc[e] += rp[(size_t)t * NEXP + e];
    }
#pragma unroll
    for (int e = 0; e < NEXP; e++) s[e][tid] = loc[e];
    __syncthreads();

    for (int str = 128; str > 0; str >>= 1) {
        if (tid < str) {
#pragma unroll
            for (int e = 0; e < NEXP; e++) s[e][tid] += s[e][tid + str];
        }
        __syncthreads();
    }
    if (tid == 0) {
        float aux = 0.f;
#pragma unroll
        for (int e = 0; e < NEXP; e++) {
            float mean = s[e][0] / (float)M_TOK;
            aux += mean * logf(mean * (float)NEXP + 1e-9f);
        }
        out[2 * D_SZ + (size_t)M_TOK * NEXP] = aux;
    }
}

// ---------------------------------------------------------------------------
extern "C" void kernel_launch(void* const* d_in, const int* in_sizes, int n_in,
                              void* d_out, int out_size)
{
    const float* x  = (const float*)d_in[0];   // hidden_states [2,2048,1024]
    const float* w1 = (const float*)d_in[1];   // [1024,1024]
    const float* b1 = (const float*)d_in[2];   // [1024]
    const float* w2 = (const float*)d_in[3];   // [8,1024]
    const float* b2 = (const float*)d_in[4];   // [8]
    float* out = (float*)d_out;

    // 1) zero dispatch + combine tensors (2*D_SZ floats, poisoned by harness)
    long n4 = (long)(2 * D_SZ / 4);
    zero_kernel<<<8192, 256>>>((float4*)out, n4);

    // 2) h = relu(x @ w1^T + b1)
    dim3 grid(HID / BN, M_TOK / BM);
    gemm_relu_kernel<<<grid, 256>>>(x, w1, b1);

    // 3) logits -> softmax -> top2 -> scatter + router_probs
    router_kernel<<<M_TOK, 256>>>(w2, b2, out);

    // 4) aux loss
    aux_kernel<<<1, 256>>>(out);
}

// round 3
// speedup vs baseline: 4.8597x; 4.8597x over previous
#include <cuda_runtime.h>
#include <cuda_bf16.h>
#include <cstdint>
#include <math.h>

// ---------------------------------------------------------------------------
// Problem constants
// ---------------------------------------------------------------------------
#define M_TOK 4096
#define HID   1024
#define NEXP  8
#define CAP   1536
static const size_t D_SZ = (size_t)M_TOK * NEXP * CAP;   // 50,331,648 per tensor

// GEMM tiling
#define BM 128
#define BN 128
#define BK 32            // bf16 k per stage
#define KTOT 3072        // 3 passes x 1024
#define NITER (KTOT / BK)        // 96
#define PITCH 40         // smem row pitch in bf16 (80 bytes) - conflict-free ldmatrix
#define TILE_BYTES (128 * PITCH * 2)   // 10240 per operand tile
#define STAGE_BYTES (2 * TILE_BYTES)   // 20480
#define SMEM_TOTAL (3 * STAGE_BYTES)   // 61440

// ---------------------------------------------------------------------------
// Device scratch
// ---------------------------------------------------------------------------
__device__ float g_h[(size_t)M_TOK * HID];                       // 16 MB
__device__ __align__(16) __nv_bfloat16 g_Ah[(size_t)M_TOK * HID]; // 8 MB
__device__ __align__(16) __nv_bfloat16 g_Al[(size_t)M_TOK * HID]; // 8 MB
__device__ __align__(16) __nv_bfloat16 g_Bh[(size_t)HID * HID];   // 2 MB
__device__ __align__(16) __nv_bfloat16 g_Bl[(size_t)HID * HID];   // 2 MB
__device__ float g_paux[32 * NEXP];

// ---------------------------------------------------------------------------
// PTX helpers (base sm_103 target: cp.async, ldmatrix, mma.sync)
// ---------------------------------------------------------------------------
__device__ __forceinline__ uint32_t smem_u32(const void* p) {
    uint32_t a;
    asm("{ .reg .u64 t; cvta.to.shared.u64 t, %1; cvt.u32.u64 %0, t; }"
        : "=r"(a) : "l"(p));
    return a;
}
__device__ __forceinline__ void cp16(uint32_t dst, const void* src) {
    asm volatile("cp.async.cg.shared.global [%0], [%1], 16;"
                 :: "r"(dst), "l"(src) : "memory");
}
__device__ __forceinline__ void cp_commit() {
    asm volatile("cp.async.commit_group;" ::: "memory");
}
__device__ __forceinline__ void cp_wait1() {
    asm volatile("cp.async.wait_group 1;" ::: "memory");
}
__device__ __forceinline__ void ldsm_x4(uint32_t& r0, uint32_t& r1,
                                        uint32_t& r2, uint32_t& r3, uint32_t a) {
    asm volatile("ldmatrix.sync.aligned.m8n8.x4.shared.b16 {%0,%1,%2,%3}, [%4];"
                 : "=r"(r0), "=r"(r1), "=r"(r2), "=r"(r3) : "r"(a));
}
__device__ __forceinline__ void mma16816(float* c, const uint32_t* a,
                                         const uint32_t* b) {
    asm volatile(
        "mma.sync.aligned.m16n8k16.row.col.f32.bf16.bf16.f32 "
        "{%0,%1,%2,%3}, {%4,%5,%6,%7}, {%8,%9}, {%0,%1,%2,%3};"
        : "+f"(c[0]), "+f"(c[1]), "+f"(c[2]), "+f"(c[3])
        : "r"(a[0]), "r"(a[1]), "r"(a[2]), "r"(a[3]), "r"(b[0]), "r"(b[1]));
}

// ---------------------------------------------------------------------------
// Split fp32 -> bf16 hi + lo (row-major, same layout as source)
// ---------------------------------------------------------------------------
__global__ void split_kernel(const float* __restrict__ x,
                             const float* __restrict__ w1) {
    uint32_t g = blockIdx.x * blockDim.x + threadIdx.x;   // 0..655359
    const uint32_t NA = (M_TOK * HID) / 8;                // 524288
    bool isA = g < NA;
    uint32_t gb = isA ? g : g - NA;
    const float* src = (isA ? x : w1) + (size_t)gb * 8;

    float4 v0 = *(const float4*)src;
    float4 v1 = *(const float4*)(src + 4);
    float f[8] = {v0.x, v0.y, v0.z, v0.w, v1.x, v1.y, v1.z, v1.w};

    uint32_t H[4], L[4];
#pragma unroll
    for (int i = 0; i < 4; i++) {
        __nv_bfloat16 h0 = __float2bfloat16(f[2*i]);
        __nv_bfloat16 h1 = __float2bfloat16(f[2*i+1]);
        __nv_bfloat16 l0 = __float2bfloat16(f[2*i]   - __bfloat162float(h0));
        __nv_bfloat16 l1 = __float2bfloat16(f[2*i+1] - __bfloat162float(h1));
        H[i] = (uint32_t)__bfloat16_as_ushort(h0) |
               ((uint32_t)__bfloat16_as_ushort(h1) << 16);
        L[i] = (uint32_t)__bfloat16_as_ushort(l0) |
               ((uint32_t)__bfloat16_as_ushort(l1) << 16);
    }
    if (isA) {
        *(uint4*)&g_Ah[(size_t)gb * 8] = make_uint4(H[0], H[1], H[2], H[3]);
        *(uint4*)&g_Al[(size_t)gb * 8] = make_uint4(L[0], L[1], L[2], L[3]);
    } else {
        *(uint4*)&g_Bh[(size_t)gb * 8] = make_uint4(H[0], H[1], H[2], H[3]);
        *(uint4*)&g_Bl[(size_t)gb * 8] = make_uint4(L[0], L[1], L[2], L[3]);
    }
}

// ---------------------------------------------------------------------------
// Fused HMMA GEMM (3-term bf16 split) + zero-fill of dispatch/combine tensors.
// C = relu(Ah*Bh + Ah*Bl + Al*Bh + bias) -> g_h
// grid (8, 32), 256 threads, occupancy 2, 3-stage cp.async pipeline.
// ---------------------------------------------------------------------------
__global__ __launch_bounds__(256, 2)
void gemm_fused_kernel(const float* __restrict__ bias, float* __restrict__ out) {
    extern __shared__ __align__(128) unsigned char smem[];
    const uint32_t sb = smem_u32(smem);

    const int tid  = threadIdx.x;
    const int wid  = tid >> 5;
    const int lane = tid & 31;
    const int nb = blockIdx.x;      // 0..7
    const int mb = blockIdx.y;      // 0..31
    const int wm = wid >> 2;        // 0..1 (64-row half)
    const int wn = wid & 3;         // 0..3 (32-col quarter)

    // per-thread load slots: 2 chunks for A, 2 for B
    const int lrow0 = tid >> 2;             // 0..63
    const int lrow1 = lrow0 + 64;           // 64..127
    const int lch   = (tid & 3);            // 16B chunk in row
    const int a_grow0 = mb * BM + lrow0, a_grow1 = mb * BM + lrow1;
    const int b_grow0 = nb * BN + lrow0, b_grow1 = nb * BN + lrow1;
    const uint32_t dA0 = lrow0 * (PITCH * 2) + lch * 16;
    const uint32_t dA1 = lrow1 * (PITCH * 2) + lch * 16;

    float acc[4][4][4];
#pragma unroll
    for (int i = 0; i < 4; i++)
#pragma unroll
        for (int j = 0; j < 4; j++)
#pragma unroll
            for (int k = 0; k < 4; k++) acc[i][j][k] = 0.f;

    auto issue_stage = [&](int kt_idx) {   // kt_idx in [0, NITER)
        int kk = kt_idx * BK;              // global k in [0, 3072)
        int p  = kk >> 10;
        int ko = (kk & 1023) + lch * 8;
        const __nv_bfloat16* sA = (p < 2) ? g_Ah : g_Al;
        const __nv_bfloat16* sB = (p == 1) ? g_Bl : g_Bh;
        uint32_t st = sb + (kt_idx % 3) * STAGE_BYTES;
        cp16(st + dA0, sA + (size_t)a_grow0 * HID + ko);
        cp16(st + dA1, sA + (size_t)a_grow1 * HID + ko);
        cp16(st + TILE_BYTES + dA0, sB + (size_t)b_grow0 * HID + ko);
        cp16(st + TILE_BYTES + dA1, sB + (size_t)b_grow1 * HID + ko);
    };

    // prologue: stages 0 and 1
    issue_stage(0); cp_commit();
    issue_stage(1); cp_commit();

    // zero-fill setup (interleaved with main loop)
    const uint32_t gtid = (uint32_t)(mb * 8 + nb) * 256u + tid;
    float4* o4 = (float4*)out;
    const float4 zf = make_float4(0.f, 0.f, 0.f, 0.f);

    // ldmatrix base addresses (per warp)
    const uint32_t a_lrow = wm * 64 + (lane & 15);
    const uint32_t a_lcol = (lane >> 4) * 8;
    const uint32_t b_q = lane >> 3, b_r = lane & 7;
    const uint32_t b_nloc = wn * 32 + (b_q >> 1) * 8 + b_r;
    const uint32_t b_kloc = (b_q & 1) * 8;

    for (int i = 0; i < NITER; i++) {
        cp_wait1();
        __syncthreads();

        if (i + 2 < NITER) issue_stage(i + 2);
        cp_commit();

        // interleaved zero-fill: 4 float4 per thread per iter
#pragma unroll
        for (int j = 0; j < 4; j++)
            o4[(size_t)(i * 4 + j) * 65536u + gtid] = zf;

        uint32_t stA = sb + (i % 3) * STAGE_BYTES;
        uint32_t stB = stA + TILE_BYTES;

#pragma unroll
        for (int kt = 0; kt < 2; kt++) {
            uint32_t af[4][4];
#pragma unroll
            for (int mt = 0; mt < 4; mt++) {
                uint32_t addr = stA + (mt * 16 + a_lrow) * (PITCH * 2)
                              + (kt * 16 + a_lcol) * 2;
                ldsm_x4(af[mt][0], af[mt][1], af[mt][2], af[mt][3], addr);
            }
            uint32_t bf[4][2];
#pragma unroll
            for (int g = 0; g < 2; g++) {
                uint32_t addr = stB + (b_nloc + g * 16) * (PITCH * 2)
                              + (kt * 16 + b_kloc) * 2;
                uint32_t r0, r1, r2, r3;
                ldsm_x4(r0, r1, r2, r3, addr);
                bf[g * 2 + 0][0] = r0; bf[g * 2 + 0][1] = r1;
                bf[g * 2 + 1][0] = r2; bf[g * 2 + 1][1] = r3;
            }
#pragma unroll
            for (int mt = 0; mt < 4; mt++)
#pragma unroll
                for (int nt = 0; nt < 4; nt++)
                    mma16816(acc[mt][nt], af[mt], bf[nt]);
        }
    }

    // epilogue: bias + relu -> g_h
    const int row_base = mb * BM + wm * 64 + (lane >> 2);
    const int col_base = nb * BN + wn * 32 + (lane & 3) * 2;
#pragma unroll
    for (int nt = 0; nt < 4; nt++) {
        int c = col_base + nt * 8;
        float b0 = __ldg(&bias[c]), b1 = __ldg(&bias[c + 1]);
#pragma unroll
        for (int mt = 0; mt < 4; mt++) {
            int r = row_base + mt * 16;
            float2 v0, v1;
            v0.x = fmaxf(acc[mt][nt][0] + b0, 0.f);
            v0.y = fmaxf(acc[mt][nt][1] + b1, 0.f);
            v1.x = fmaxf(acc[mt][nt][2] + b0, 0.f);
            v1.y = fmaxf(acc[mt][nt][3] + b1, 0.f);
            *(float2*)&g_h[(size_t)r * HID + c]       = v0;
            *(float2*)&g_h[(size_t)(r + 8) * HID + c] = v1;
        }
    }
}

// ---------------------------------------------------------------------------
// Router: per-token logits, softmax, top-2 scatter, router_probs.
// ---------------------------------------------------------------------------
__global__ void router_kernel(const float* __restrict__ w2,
                              const float* __restrict__ b2,
                              float* __restrict__ out) {
    const int m   = blockIdx.x;
    const int tid = threadIdx.x;

    __shared__ __align__(16) float hs[HID];
    __shared__ float logits[NEXP];

    const float4* hrow = (const float4*)&g_h[(size_t)m * HID];
    ((float4*)hs)[tid] = hrow[tid];
    __syncthreads();

    const int e    = tid >> 5;
    const int lane = tid & 31;
    const float4* w2row = (const float4*)&w2[(size_t)e * HID];
    const float4* hs4   = (const float4*)hs;

    float sum = 0.f;
#pragma unroll
    for (int i = 0; i < 8; i++) {
        float4 a = hs4[lane + i * 32];
        float4 b = w2row[lane + i * 32];
        sum += a.x * b.x + a.y * b.y + a.z * b.z + a.w * b.w;
    }
#pragma unroll
    for (int off = 16; off > 0; off >>= 1)
        sum += __shfl_xor_sync(0xFFFFFFFFu, sum, off);
    if (lane == 0) logits[e] = sum + b2[e];
    __syncthreads();

    if (tid == 0) {
        float l[NEXP], p[NEXP];
        float mx = -1e30f;
#pragma unroll
        for (int i = 0; i < NEXP; i++) { l[i] = logits[i]; mx = fmaxf(mx, l[i]); }
        float s = 0.f;
#pragma unroll
        for (int i = 0; i < NEXP; i++) { p[i] = expf(l[i] - mx); s += p[i]; }
        float inv = 1.f / s;
#pragma unroll
        for (int i = 0; i < NEXP; i++) p[i] *= inv;

        float* rp = out + 2 * D_SZ + (size_t)m * NEXP;
#pragma unroll
        for (int i = 0; i < NEXP; i++) rp[i] = p[i];

        int i1 = 0;
#pragma unroll
        for (int i = 1; i < NEXP; i++) if (p[i] > p[i1]) i1 = i;
        int i2 = -1;
#pragma unroll
        for (int i = 0; i < NEXP; i++) {
            if (i == i1) continue;
            if (i2 < 0 || p[i] > p[i2]) i2 = i;
        }
        float denom = p[i1] + p[i2];

        size_t base = (size_t)m * NEXP * CAP;
        out[base + (size_t)i1 * CAP] = 1.0f;
        out[base + (size_t)i2 * CAP] = 1.0f;
        out[D_SZ + base + (size_t)i1 * CAP] = p[i1] / denom;
        out[D_SZ + base + (size_t)i2 * CAP] = p[i2] / denom;
    }
}

// ---------------------------------------------------------------------------
// Aux loss: two-stage deterministic reduction.
// ---------------------------------------------------------------------------
__global__ void aux1_kernel(const float* __restrict__ out) {
    __shared__ float s[NEXP][128];
    int tid = threadIdx.x;
    int t = blockIdx.x * 128 + tid;
    const float* rp = out + 2 * D_SZ + (size_t)t * NEXP;
    float4 a = *(const float4*)rp;
    float4 b = *(const float4*)(rp + 4);
    s[0][tid] = a.x; s[1][tid] = a.y; s[2][tid] = a.z; s[3][tid] = a.w;
    s[4][tid] = b.x; s[5][tid] = b.y; s[6][tid] = b.z; s[7][tid] = b.w;
    __syncthreads();
    for (int str = 64; str > 0; str >>= 1) {
        if (tid < str) {
#pragma unroll
            for (int e = 0; e < NEXP; e++) s[e][tid] += s[e][tid + str];
        }
        __syncthreads();
    }
    if (tid < NEXP) g_paux[blockIdx.x * NEXP + tid] = s[tid][0];
}

__global__ void aux2_kernel(float* __restrict__ out) {
    int tid = threadIdx.x;
    int e = tid >> 5, lane = tid & 31;
    __shared__ float se[NEXP];
    float v = g_paux[lane * NEXP + e];
#pragma unroll
    for (int off = 16; off > 0; off >>= 1)
        v += __shfl_xor_sync(0xFFFFFFFFu, v, off);
    if (lane == 0) se[e] = v;
    __syncthreads();
    if (tid == 0) {
        float aux = 0.f;
#pragma unroll
        for (int i = 0; i < NEXP; i++) {
            float mean = se[i] / (float)M_TOK;
            aux += mean * logf(mean * (float)NEXP + 1e-9f);
        }
        out[2 * D_SZ + (size_t)M_TOK * NEXP] = aux;
    }
}

// ---------------------------------------------------------------------------
extern "C" void kernel_launch(void* const* d_in, const int* in_sizes, int n_in,
                              void* d_out, int out_size)
{
    const float* x  = (const float*)d_in[0];
    const float* w1 = (const float*)d_in[1];
    const float* b1 = (const float*)d_in[2];
    const float* w2 = (const float*)d_in[3];
    const float* b2 = (const float*)d_in[4];
    float* out = (float*)d_out;

    cudaFuncSetAttribute(gemm_fused_kernel,
                         cudaFuncAttributeMaxDynamicSharedMemorySize, SMEM_TOTAL);

    // 1) split fp32 -> bf16 hi/lo
    split_kernel<<<2560, 256>>>(x, w1);

    // 2) fused GEMM (+bias+ReLU -> g_h) + zero-fill of out
    dim3 grid(HID / BN, M_TOK / BM);   // (8, 32)
    gemm_fused_kernel<<<grid, 256, SMEM_TOTAL>>>(b1, out);

    // 3) router
    router_kernel<<<M_TOK, 256>>>(w2, b2, out);

    // 4) aux loss
    aux1_kernel<<<32, 128>>>(out);
    aux2_kernel<<<1, 256>>>(out);
}